// round 7
// baseline (speedup 1.0000x reference)
#include <cuda_runtime.h>
#include <stdint.h>

// ProbabilisticPrediction fused kernel, R7: R=4 rows/block, 512 threads,
// 2 blocks/SM (barrier decoupling), f-gather hidden under layer1 q-part,
// eps precomputed in phase 1, merged layer3 reduce+sample.
// Gumbel-argmax (JAX threefry partitionable) selects one mixture component
// per (b,q); the 3-layer MLP is evaluated only at those 1024 points.

#define B_   4
#define QL_  256
#define CL_  512
#define DIM_ 128
#define YD_  16
#define R_   4

// ---------------------------------------------------------------- threefry2x32
__host__ __device__ inline void tf2x32(uint32_t k0, uint32_t k1,
                                       uint32_t c0, uint32_t c1,
                                       uint32_t& o0, uint32_t& o1) {
    uint32_t k2 = k0 ^ k1 ^ 0x1BD11BDAu;
    uint32_t x0 = c0 + k0, x1 = c1 + k1;
#define TFR(d) do { x0 += x1; x1 = (x1 << (d)) | (x1 >> (32 - (d))); x1 ^= x0; } while (0)
    TFR(13); TFR(15); TFR(26); TFR(6);   x0 += k1; x1 += k2 + 1u;
    TFR(17); TFR(29); TFR(16); TFR(24);  x0 += k2; x1 += k0 + 2u;
    TFR(13); TFR(15); TFR(26); TFR(6);   x0 += k0; x1 += k1 + 3u;
    TFR(17); TFR(29); TFR(16); TFR(24);  x0 += k1; x1 += k2 + 4u;
    TFR(13); TFR(15); TFR(26); TFR(6);   x0 += k2; x1 += k0 + 5u;
#undef TFR
    o0 = x0; o1 = x1;
}

__device__ inline uint32_t jax_bits(uint32_t k0, uint32_t k1, uint32_t j) {
    uint32_t o0, o1;
    tf2x32(k0, k1, 0u, j, o0, o1);   // partitionable: 64-bit iota (0, j)
    return o0 ^ o1;
}

__device__ inline float bits_to_unit(uint32_t b) {      // [0, 1)
    return __uint_as_float((b >> 9) | 0x3f800000u) - 1.0f;
}

// XLA ErfInv32 (Giles) -- matches jax.random.normal exactly.
__device__ inline float erfinv_xla(float x) {
    float w = -log1pf(-x * x);
    float p;
    if (w < 5.0f) {
        w -= 2.5f;
        p =            2.81022636e-08f;
        p = fmaf(p, w, 3.43273939e-07f);
        p = fmaf(p, w, -3.5233877e-06f);
        p = fmaf(p, w, -4.39150654e-06f);
        p = fmaf(p, w, 0.00021858087f);
        p = fmaf(p, w, -0.00125372503f);
        p = fmaf(p, w, -0.00417768164f);
        p = fmaf(p, w, 0.246640727f);
        p = fmaf(p, w, 1.50140941f);
    } else {
        w = sqrtf(w) - 3.0f;
        p =            -0.000200214257f;
        p = fmaf(p, w, 0.000100950558f);
        p = fmaf(p, w, 0.00134934322f);
        p = fmaf(p, w, -0.00367342844f);
        p = fmaf(p, w, 0.00573950773f);
        p = fmaf(p, w, -0.0076224613f);
        p = fmaf(p, w, 0.00943887047f);
        p = fmaf(p, w, 1.00167406f);
        p = fmaf(p, w, 2.83297682f);
    }
    return p * x;
}

// ---------------------------------------------------------------------- kernel
__global__ __launch_bounds__(512, 2)
void pp_fused_kernel(const float* __restrict__ q,
                     const float* __restrict__ f_embed,
                     const float* __restrict__ att_logits,
                     const float* __restrict__ W1q,
                     const float* __restrict__ W1f,
                     const float* __restrict__ b1,
                     const float* __restrict__ W2,
                     const float* __restrict__ b2,
                     const float* __restrict__ Wout,
                     const float* __restrict__ bout,
                     float* __restrict__ out,
                     uint32_t kc0, uint32_t kc1,
                     uint32_t ke0, uint32_t ke1)
{
    const int t   = threadIdx.x;         // 0..511
    const int w   = t >> 5;              // warp 0..15
    const int ln  = t & 31;
    const int bq0 = blockIdx.x * R_;
    const int b   = bq0 >> 8;            // all R_ rows share b (4 | 256)

    __shared__ float sQ[R_ * DIM_];      // q rows; later h2
    __shared__ float sF[R_ * DIM_];      // selected f rows
    __shared__ float sH[R_ * DIM_];      // h1
    __shared__ float sPar[4 * R_ * DIM_];// partials (8KB); reused in layer3
    __shared__ float sVal[16];
    __shared__ int   sIdxW[16];

    // Prefetch q rows (hidden under phase-1 ALU).
    if (t < 128)
        ((float4*)sQ)[t] = ((const float4*)(q + (size_t)bq0 * DIM_))[t];

    // -------- Phase 1: Gumbel-argmax; row r = w>>2, sub-range sub = w&3 -----
    {
        const int r = w >> 2, sub = w & 3;
        const int bq = bq0 + r;
        const float* lrow = att_logits + (size_t)bq * CL_;
        const float TINY = 1.17549435e-38f;
        float best = -__int_as_float(0x7f800000);
        int bi = 0;
#pragma unroll
        for (int i = 0; i < 4; ++i) {
            int c = sub * 128 + i * 32 + ln;
            uint32_t j = (uint32_t)bq * (uint32_t)CL_ + (uint32_t)c;
            float u = bits_to_unit(jax_bits(kc0, kc1, j));
            u = fmaxf(TINY, u * (1.0f - TINY) + TINY);
            // g = -log(-log(u)) = -ln2*log2(-log2(u)) - ln(ln2)
            float lg1; asm("lg2.approx.f32 %0, %1;" : "=f"(lg1) : "f"(u));
            float L = -lg1;
            float lg2v; asm("lg2.approx.f32 %0, %1;" : "=f"(lg2v) : "f"(L));
            float g = fmaf(-0.693147180559945f, lg2v, 0.366512920581664f);
            float v = g + lrow[c];
            if (v > best || (v == best && c < bi)) { best = v; bi = c; }
        }
#pragma unroll
        for (int off = 16; off; off >>= 1) {
            float v2 = __shfl_xor_sync(0xffffffffu, best, off);
            int   i2 = __shfl_xor_sync(0xffffffffu, bi,   off);
            if (v2 > best || (v2 == best && i2 < bi)) { best = v2; bi = i2; }
        }
        if (ln == 0) { sVal[w] = best; sIdxW[w] = bi; }
    }

    // Precompute eps for the sample stage (held in a register until the end).
    float epsv = 0.f;
    if (t < R_ * YD_) {                  // 64 threads
        uint32_t m = (uint32_t)(bq0 + (t >> 4)) * (uint32_t)YD_ + (uint32_t)(t & 15);
        float u = bits_to_unit(jax_bits(ke0, ke1, m));
        const float lo = -0.99999994f;
        float x = fmaxf(lo, u * (1.0f - lo) + lo);
        epsv = 1.41421356237f * erfinv_xla(x);
    }
    __syncthreads();                     // A: sVal/sIdxW + sQ visible

    // Warps 0-3 finalize their row's argmax and start the f-row gather; the
    // gather's LDG latency hides under the layer-1 q-part below.
    float4 fgv;
    const bool gat = (t < 128);
    if (gat) {
        const int r = w;                 // 0..3
        float bv = sVal[r * 4]; int bj = sIdxW[r * 4];
#pragma unroll
        for (int k = 1; k < 4; ++k) {
            float v2 = sVal[r * 4 + k]; int i2 = sIdxW[r * 4 + k];
            if (v2 > bv || (v2 == bv && i2 < bj)) { bv = v2; bj = i2; }
        }
        fgv = ((const float4*)(f_embed + ((size_t)b * CL_ + bj) * DIM_))[ln];
    }

    const int c   = t & 127;             // output column
    const int oct = t >> 7;              // d-quarter 0..3 (32 d's each)
    float acc[R_] = {0.f, 0.f, 0.f, 0.f};

    // -------- Layer 1, q-part: acc += q@W1q (pipelined weight loads) --------
    {
        const float* wq = W1q + c;
        float c0, c1, c2, c3;
        {
            const int d = oct * 32;
            c0 = wq[(d + 0) * DIM_]; c1 = wq[(d + 1) * DIM_];
            c2 = wq[(d + 2) * DIM_]; c3 = wq[(d + 3) * DIM_];
        }
#pragma unroll
        for (int i = 0; i < 8; ++i) {
            float n0, n1, n2, n3;
            if (i < 7) {
                const int dn = oct * 32 + (i + 1) * 4;
                n0 = wq[(dn + 0) * DIM_]; n1 = wq[(dn + 1) * DIM_];
                n2 = wq[(dn + 2) * DIM_]; n3 = wq[(dn + 3) * DIM_];
            }
            const int d = oct * 32 + i * 4;
#pragma unroll
            for (int r = 0; r < R_; ++r) {
                float4 qv = ((const float4*)sQ)[r * 32 + (d >> 2)];
                acc[r] = fmaf(qv.x, c0, acc[r]); acc[r] = fmaf(qv.y, c1, acc[r]);
                acc[r] = fmaf(qv.z, c2, acc[r]); acc[r] = fmaf(qv.w, c3, acc[r]);
            }
            if (i < 7) { c0 = n0; c1 = n1; c2 = n2; c3 = n3; }
        }
    }
    if (gat) ((float4*)(sF + w * DIM_))[ln] = fgv;
    __syncthreads();                     // B: sF visible

    // -------- Layer 1, f-part: acc += f@W1f; store partials -----------------
    {
        const float* wf = W1f + c;
        float c0, c1, c2, c3;
        {
            const int d = oct * 32;
            c0 = wf[(d + 0) * DIM_]; c1 = wf[(d + 1) * DIM_];
            c2 = wf[(d + 2) * DIM_]; c3 = wf[(d + 3) * DIM_];
        }
#pragma unroll
        for (int i = 0; i < 8; ++i) {
            float n0, n1, n2, n3;
            if (i < 7) {
                const int dn = oct * 32 + (i + 1) * 4;
                n0 = wf[(dn + 0) * DIM_]; n1 = wf[(dn + 1) * DIM_];
                n2 = wf[(dn + 2) * DIM_]; n3 = wf[(dn + 3) * DIM_];
            }
            const int d = oct * 32 + i * 4;
#pragma unroll
            for (int r = 0; r < R_; ++r) {
                float4 fv = ((const float4*)sF)[r * 32 + (d >> 2)];
                acc[r] = fmaf(fv.x, c0, acc[r]); acc[r] = fmaf(fv.y, c1, acc[r]);
                acc[r] = fmaf(fv.z, c2, acc[r]); acc[r] = fmaf(fv.w, c3, acc[r]);
            }
            if (i < 7) { c0 = n0; c1 = n1; c2 = n2; c3 = n3; }
        }
#pragma unroll
        for (int r = 0; r < R_; ++r) sPar[oct * 512 + r * DIM_ + c] = acc[r];
    }
    __syncthreads();                     // C
    {
        float s = sPar[t] + sPar[512 + t] + sPar[1024 + t] + sPar[1536 + t];
        sH[t] = fmaxf(s + b1[c], 0.f);
    }
    __syncthreads();                     // D

    // -------- Layer 2: h2 = relu(h@W2 + b2), pipelined loads ----------------
    {
#pragma unroll
        for (int r = 0; r < R_; ++r) acc[r] = 0.f;
        const float* w2 = W2 + c;
        float c0, c1, c2, c3;
        {
            const int d = oct * 32;
            c0 = w2[(d + 0) * DIM_]; c1 = w2[(d + 1) * DIM_];
            c2 = w2[(d + 2) * DIM_]; c3 = w2[(d + 3) * DIM_];
        }
#pragma unroll
        for (int i = 0; i < 8; ++i) {
            float n0, n1, n2, n3;
            if (i < 7) {
                const int dn = oct * 32 + (i + 1) * 4;
                n0 = w2[(dn + 0) * DIM_]; n1 = w2[(dn + 1) * DIM_];
                n2 = w2[(dn + 2) * DIM_]; n3 = w2[(dn + 3) * DIM_];
            }
            const int d = oct * 32 + i * 4;
#pragma unroll
            for (int r = 0; r < R_; ++r) {
                float4 hv = ((const float4*)sH)[r * 32 + (d >> 2)];
                acc[r] = fmaf(hv.x, c0, acc[r]); acc[r] = fmaf(hv.y, c1, acc[r]);
                acc[r] = fmaf(hv.z, c2, acc[r]); acc[r] = fmaf(hv.w, c3, acc[r]);
            }
            if (i < 7) { c0 = n0; c1 = n1; c2 = n2; c3 = n3; }
        }
#pragma unroll
        for (int r = 0; r < R_; ++r) sPar[oct * 512 + r * DIM_ + c] = acc[r];
    }
    __syncthreads();                     // E
    {
        float s = sPar[t] + sPar[512 + t] + sPar[1024 + t] + sPar[1536 + t];
        sQ[t] = fmaxf(s + b2[c], 0.f);   // sQ := h2
    }
    __syncthreads();                     // F

    // -------- Layer 3: partials (o = ln, g = w: 8 d's each, all 4 rows) -----
    {
        const int o = ln;                // output column 0..31
        const int g = w;                 // d-group 0..15
        float wv0 = Wout[(g * 8 + 0) * 32 + o], wv1 = Wout[(g * 8 + 1) * 32 + o];
        float wv2 = Wout[(g * 8 + 2) * 32 + o], wv3 = Wout[(g * 8 + 3) * 32 + o];
        float wv4 = Wout[(g * 8 + 4) * 32 + o], wv5 = Wout[(g * 8 + 5) * 32 + o];
        float wv6 = Wout[(g * 8 + 6) * 32 + o], wv7 = Wout[(g * 8 + 7) * 32 + o];
#pragma unroll
        for (int r = 0; r < R_; ++r) {
            float4 h0 = ((const float4*)sQ)[r * 32 + g * 2];
            float4 h1 = ((const float4*)sQ)[r * 32 + g * 2 + 1];
            float a0 = fmaf(h0.x, wv0, fmaf(h0.y, wv1, 0.f));
            float a1 = fmaf(h0.z, wv2, fmaf(h0.w, wv3, 0.f));
            float a2 = fmaf(h1.x, wv4, fmaf(h1.y, wv5, 0.f));
            float a3 = fmaf(h1.z, wv6, fmaf(h1.w, wv7, 0.f));
            sPar[g * 128 + r * 32 + o] = (a0 + a1) + (a2 + a3);
        }
    }
    __syncthreads();                     // G

    // -------- Tail: reduce mu/s + sample (eps precomputed) ------------------
    if (t < R_ * YD_) {                  // 64 threads
        const int rr = t >> 4, y = t & 15;
        float mu = bout[y];
        float sv = bout[YD_ + y];
#pragma unroll
        for (int g = 0; g < 16; ++g) {
            mu += sPar[g * 128 + rr * 32 + y];
            sv += sPar[g * 128 + rr * 32 + YD_ + y];
        }
        float s = fmaxf(-15.0f, sv);
        float sigma = fmaxf(s, 0.0f) + log1pf(expf(-fabsf(s)));
        out[(size_t)bq0 * YD_ + t] = fmaf(sigma, epsv, mu);
    }
}

// ---------------------------------------------------------------------- launch
extern "C" void kernel_launch(void* const* d_in, const int* in_sizes, int n_in,
                              void* d_out, int out_size) {
    const float* q     = (const float*)d_in[0];
    const float* f_emb = (const float*)d_in[1];
    const float* alog  = (const float*)d_in[2];
    const float* W1q   = (const float*)d_in[3];
    const float* W1f   = (const float*)d_in[4];
    const float* b1    = (const float*)d_in[5];
    const float* W2    = (const float*)d_in[6];
    const float* b2    = (const float*)d_in[7];
    const float* Wout  = (const float*)d_in[8];
    const float* bout  = (const float*)d_in[9];
    float* out = (float*)d_out;

    // split(jax.random.key(1), 2), partitionable: subkey_i = tf(key, (0, i))
    uint32_t kc0, kc1, ke0, ke1;
    tf2x32(0u, 1u, 0u, 0u, kc0, kc1);
    tf2x32(0u, 1u, 0u, 1u, ke0, ke1);

    pp_fused_kernel<<<(B_ * QL_) / R_, 512>>>(q, f_emb, alog, W1q, W1f, b1,
                                              W2, b2, Wout, bout, out,
                                              kc0, kc1, ke0, ke1);
}